// round 14
// baseline (speedup 1.0000x reference)
#include <cuda_runtime.h>
#include <math.h>

// Problem constants: B=4, S=4096, H=2048, E=8, K=2
#define T_TOKENS 16384
#define HDIM     2048
#define NEXP     8
#define TOPK     2
#define H4       (HDIM / 4)   // 512 float4 per row
#define TPW      16           // tokens per warp
#define DEPTH    8            // smem ring depth (stages)
#define NSTAGE   (H4 / 8)     // 64 stages: 8 float4 of H per token per stage
#define WARPS    2            // warps per CTA

// Zero-initialized at module load; last block re-zeros after each use so
// every graph replay sees a clean state (deterministic).
__device__ int g_counts[NEXP];
__device__ unsigned int g_done;

// Packed f32x2 FMA: d = a*b + d elementwise on packed pairs (verified R2).
#define FMA_F32X2(d, a, b) \
    asm("fma.rn.f32x2 %0, %1, %2, %0;" : "+l"(d) : "l"(a), "l"(b))
#define UNPACK_F32X2(lo, hi, in) \
    asm("mov.b64 {%0, %1}, %2;" : "=f"(lo), "=f"(hi) : "l"(in))

// Self-feeding deep pipeline: each warp streams its 16 tokens' x through a
// private depth-8 smem ring with per-lane cp.async + commit_group/wait_group.
// 7 stages x 2KB always in flight per warp -> DRAM concurrency no longer
// capped by the register file (R7's limit) and no mbarrier/TMA per-op
// overhead (R12's limit). Quarter-warp expert split: 8-lane group g owns
// experts 2g, 2g+1; packed f32x2 accumulators (64 regs).
__global__ __launch_bounds__(64, 7)
void router_kernel(const float* __restrict__ x,
                   const float* __restrict__ gate_w,
                   float* __restrict__ out) {
    // [warp][slot][tok][8 float4] = 2 warps x 8 slots x 2KB = 32 KB
    __shared__ float4 s_x[WARPS][DEPTH][TPW][8];
    __shared__ int s_counts[NEXP];
    const int tid = threadIdx.x;
    if (tid < NEXP) s_counts[tid] = 0;
    __syncthreads();

    const int lane = tid & 31;
    const int wid  = tid >> 5;
    const int grp  = lane >> 3;        // expert-pair group 0..3
    const int k    = lane & 7;         // position within group
    const int warp_global = blockIdx.x * WARPS + wid;
    const int t0   = warp_global * TPW;

    // Producer-side mapping: chunk c = lane + 32q -> (tok = c>>3, pos = c&7).
    const int ptok = lane >> 3;
    const int ppos = lane & 7;
    const float4* __restrict__ src0 =
        (const float4*)x + (size_t)(t0 + ptok) * H4 + ppos;
    const unsigned dst0 =
        (unsigned)__cvta_generic_to_shared(&s_x[wid][0][0][0])
        + (unsigned)(ptok * 128 + ppos * 16);

    // Issue one 2KB stage: 4 x 16B cp.async per lane (tokens ptok+4q).
#define ISSUE_STAGE(S)                                                       \
    do {                                                                     \
        const unsigned _d = dst0 + (unsigned)(((S) & (DEPTH - 1)) * (TPW*128)); \
        const float4* _s = src0 + 8 * (S);                                   \
        _Pragma("unroll")                                                    \
        for (int q = 0; q < 4; q++)                                          \
            asm volatile("cp.async.cg.shared.global [%0], [%1], 16;"         \
                         :: "r"(_d + (unsigned)(q * 512)),                   \
                            "l"(_s + (size_t)q * (4 * H4)) : "memory");      \
        asm volatile("cp.async.commit_group;" ::: "memory");                 \
    } while (0)

    // Prologue: fill 7 stages (ring holds 8; slot s consumed before s+8 issued).
    #pragma unroll
    for (int s = 0; s < DEPTH - 1; s++) ISSUE_STAGE(s);

    const ulonglong2* __restrict__ w2 = (const ulonglong2*)gate_w;
    const ulonglong2* __restrict__ w0p = w2 + (size_t)(2 * grp)     * H4 + k;
    const ulonglong2* __restrict__ w1p = w2 + (size_t)(2 * grp + 1) * H4 + k;

    // acc[2m+j]: token m, expert 2*grp+j, packed pair over H (64 regs).
    unsigned long long acc[TPW * 2];
    #pragma unroll
    for (int p = 0; p < TPW * 2; p++) acc[p] = 0ULL;

    #pragma unroll 1
    for (int s = 0; s < NSTAGE; s++) {
        // Keep exactly 8 groups outstanding; empty commits pad the tail so
        // wait_group 7 always completes stage s.
        if (s + DEPTH - 1 < NSTAGE) {
            ISSUE_STAGE(s + DEPTH - 1);
        } else {
            asm volatile("cp.async.commit_group;" ::: "memory");
        }
        asm volatile("cp.async.wait_group %0;" :: "n"(DEPTH - 1) : "memory");

        const int slot = s & (DEPTH - 1);
        ulonglong2 wv0 = __ldg(w0p + 8 * s);
        ulonglong2 wv1 = __ldg(w1p + 8 * s);

        #pragma unroll
        for (int m = 0; m < TPW; m++) {
            ulonglong2 xv = *(const ulonglong2*)&s_x[wid][slot][m][k];
            FMA_F32X2(acc[2 * m],     xv.x, wv0.x);
            FMA_F32X2(acc[2 * m],     xv.y, wv0.y);
            FMA_F32X2(acc[2 * m + 1], xv.x, wv1.x);
            FMA_F32X2(acc[2 * m + 1], xv.y, wv1.y);
        }
    }
#undef ISSUE_STAGE

    // Collapse packed pairs: r[2m+j] = partial logit(token m, expert 2grp+j).
    float r[TPW * 2];
    #pragma unroll
    for (int p = 0; p < TPW * 2; p++) {
        float lo, hi;
        UNPACK_F32X2(lo, hi, acc[p]);
        r[p] = lo + hi;
    }

    // Full butterfly over each 8-lane group (offsets 4,2,1): every lane of
    // group grp then holds the complete logits for experts 2grp, 2grp+1.
    #pragma unroll
    for (int p = 0; p < TPW * 2; p++) {
        r[p] += __shfl_xor_sync(0xFFFFFFFFu, r[p], 4);
        r[p] += __shfl_xor_sync(0xFFFFFFFFu, r[p], 2);
        r[p] += __shfl_xor_sync(0xFFFFFFFFu, r[p], 1);
    }

    // Gather: for each token m (static), pull its 8 logits from lanes
    // 0/8/16/24 (one per expert pair); lane m keeps them (value selects,
    // all static register indices).
    float l[NEXP];
    #pragma unroll
    for (int e = 0; e < NEXP; e++) l[e] = 0.0f;
    #pragma unroll
    for (int m = 0; m < TPW; m++) {
        float lm[NEXP];
        lm[0] = __shfl_sync(0xFFFFFFFFu, r[2 * m],     0);
        lm[1] = __shfl_sync(0xFFFFFFFFu, r[2 * m + 1], 0);
        lm[2] = __shfl_sync(0xFFFFFFFFu, r[2 * m],     8);
        lm[3] = __shfl_sync(0xFFFFFFFFu, r[2 * m + 1], 8);
        lm[4] = __shfl_sync(0xFFFFFFFFu, r[2 * m],     16);
        lm[5] = __shfl_sync(0xFFFFFFFFu, r[2 * m + 1], 16);
        lm[6] = __shfl_sync(0xFFFFFFFFu, r[2 * m],     24);
        lm[7] = __shfl_sync(0xFFFFFFFFu, r[2 * m + 1], 24);
        #pragma unroll
        for (int e = 0; e < NEXP; e++)
            l[e] = (lane == m) ? lm[e] : l[e];
    }

    if (lane < TPW) {
        const int t = t0 + lane;

        // top-1 (strict > keeps lowest index on tie, matching jax top_k)
        float m1 = l[0]; int i1 = 0;
        #pragma unroll
        for (int e = 1; e < NEXP; e++)
            if (l[e] > m1) { m1 = l[e]; i1 = e; }
        // top-2
        float m2 = -INFINITY; int i2 = 0;
        #pragma unroll
        for (int e = 0; e < NEXP; e++)
            if (e != i1 && l[e] > m2) { m2 = l[e]; i2 = e; }

        // renormalized top-2 softmax weights
        float e2  = __expf(m2 - m1);    // <= 1, numerically safe
        float inv = 1.0f / (1.0f + e2);

        out[(size_t)t * TOPK + 0] = inv;
        out[(size_t)t * TOPK + 1] = e2 * inv;
        out[(size_t)T_TOKENS * TOPK + (size_t)t * TOPK + 0] = (float)i1;
        out[(size_t)T_TOKENS * TOPK + (size_t)t * TOPK + 1] = (float)i2;

        atomicAdd(&s_counts[i1], 1);
        atomicAdd(&s_counts[i2], 1);
    }

    __syncthreads();
    if (tid < NEXP)
        atomicAdd(&g_counts[tid], s_counts[tid]);
    __threadfence();
    __syncthreads();

    // Last block computes the aux loss and resets global state.
    if (tid == 0) {
        unsigned int prev = atomicAdd(&g_done, 1u);
        if (prev == gridDim.x - 1) {
            volatile int* vc = (volatile int*)g_counts;
            float mpe[NEXP];
            float mu = 0.0f;
            #pragma unroll
            for (int e = 0; e < NEXP; e++) {
                mpe[e] = (float)vc[e] / (float)T_TOKENS;
                mu += mpe[e];
            }
            mu *= (1.0f / NEXP);
            float v = 0.0f;
            #pragma unroll
            for (int e = 0; e < NEXP; e++) {
                float d = mpe[e] - mu;
                v += d * d;
            }
            v *= (1.0f / (NEXP - 1));   // unbiased variance (ddof=1)
            out[(size_t)T_TOKENS * TOPK * 2] = v * (float)NEXP;

            // Reset for the next graph replay.
            #pragma unroll
            for (int e = 0; e < NEXP; e++) g_counts[e] = 0;
            g_done = 0u;
        }
    }
}

extern "C" void kernel_launch(void* const* d_in, const int* in_sizes, int n_in,
                              void* d_out, int out_size) {
    const float* x      = (const float*)d_in[0];   // (B,S,H) = (T, H)
    const float* gate_w = (const float*)d_in[1];   // (E, H)
    float* out = (float*)d_out;

    router_kernel<<<T_TOKENS / (TPW * WARPS), 64>>>(x, gate_w, out);
}